// round 6
// baseline (speedup 1.0000x reference)
#include <cuda_runtime.h>
#include <cuda_bf16.h>

// Problem constants (sized for this dataset; runtime values read from in_sizes)
#define N_MAX 100000
#define E_MAX 1600000
#define DIM 128

// Scratch (static device allocations — no runtime alloc allowed)
__device__ float g_dinv[N_MAX];          // degree, then D^-1/2 in place
__device__ int   g_cnt[N_MAX];           // histogram / placement counters
__device__ int   g_rowptr[N_MAX + 1];    // CSR row pointers (by destination col)
__device__ int   g_bsum[128];            // scan block sums
__device__ int   g_is64;                 // edge_index dtype flag (1 = int64)
__device__ int   g_src[E_MAX];           // CSR: source node per edge
__device__ float g_nrm[E_MAX];           // CSR: norm coefficient per edge
__device__ float g_H[N_MAX * DIM];       // post-GEMM features
__device__ float g_Z[N_MAX * DIM];       // layer-1 output

// Read edge_index element at flat position p under either dtype
__device__ __forceinline__ int eidx(const void* ei, int is64, int p) {
    return is64 ? (int)((const long long*)ei)[p] : ((const int*)ei)[p];
}

// ---------------------------------------------------------------------------
// Probe: decide whether edge_index is int64 or int32.
// int32 data viewed as int64 packs two ids -> values >= 2^32 (never all < N).
__global__ void probe_kernel(const long long* __restrict__ ei, int N,
                             int* __restrict__ flag) {
    if (threadIdx.x == 0) {
        int ok = 1;
        for (int i = 0; i < 64; i++) {
            long long v = ei[i];
            if (v < 0 || v >= (long long)N) { ok = 0; break; }
        }
        *flag = ok;
    }
}

// Zero-fill (graph memset nodes can't target __device__ symbols)
__global__ void zero_kernel(float* __restrict__ deg, int* __restrict__ cnt, int N) {
    int i = blockIdx.x * blockDim.x + threadIdx.x;
    if (i < N) { deg[i] = 0.f; cnt[i] = 0; }
}

// ---------------------------------------------------------------------------
// Pass 1: degree (with edge weights) + histogram of destination counts
__global__ void deg_hist_kernel(const void* __restrict__ ei,
                                const float* __restrict__ ew,
                                const int* __restrict__ flag,
                                float* __restrict__ deg, int* __restrict__ cnt,
                                int E) {
    int e = blockIdx.x * blockDim.x + threadIdx.x;
    if (e >= E) return;
    int is64 = *flag;
    int c = eidx(ei, is64, E + e);   // col = destination
    atomicAdd(&deg[c], ew[e]);
    atomicAdd(&cnt[c], 1);
}

// Pass 2: add self-loop weight, convert to D^-1/2 in place
__global__ void dinv_kernel(float* __restrict__ deg, int N) {
    int i = blockIdx.x * blockDim.x + threadIdx.x;
    if (i >= N) return;
    float d = deg[i] + 1.0f;         // self loop weight 1
    deg[i] = (d > 0.f) ? rsqrtf(d) : 0.f;
}

// Block-wise exclusive scan (Hillis-Steele), 1024 elems/block
__global__ void scan_block_kernel(const int* __restrict__ cnt,
                                  int* __restrict__ rowptr,
                                  int* __restrict__ bsum, int N) {
    __shared__ int s[1024];
    int i = blockIdx.x * 1024 + threadIdx.x;
    int v = (i < N) ? cnt[i] : 0;
    s[threadIdx.x] = v;
    __syncthreads();
    for (int off = 1; off < 1024; off <<= 1) {
        int t = (threadIdx.x >= off) ? s[threadIdx.x - off] : 0;
        __syncthreads();
        s[threadIdx.x] += t;
        __syncthreads();
    }
    if (i < N) rowptr[i] = s[threadIdx.x] - v;   // exclusive
    if (threadIdx.x == 1023) bsum[blockIdx.x] = s[1023];
}

// Sequential scan of block sums (<=128 values)
__global__ void scan_sums_kernel(int* __restrict__ bsum, int nblk) {
    int run = 0;
    for (int b = 0; b < nblk; b++) {
        int t = bsum[b];
        bsum[b] = run;
        run += t;
    }
}

// Add scanned block offsets; also re-zero cnt for the placement pass.
__global__ void add_off_kernel(int* __restrict__ rowptr,
                               const int* __restrict__ bsum,
                               int* __restrict__ cnt, int N, int E) {
    int i = blockIdx.x * blockDim.x + threadIdx.x;
    if (i < N) {
        rowptr[i] += bsum[i >> 10];
        cnt[i] = 0;
    }
    if (i == 0) rowptr[N] = E;
}

// Pass 3: place edges into CSR slots, precompute per-edge norm
__global__ void place_kernel(const void* __restrict__ ei,
                             const float* __restrict__ ew,
                             const int* __restrict__ flag,
                             const float* __restrict__ dinv,
                             const int* __restrict__ rowptr,
                             int* __restrict__ cnt,
                             int* __restrict__ srcv, float* __restrict__ nrm,
                             int E) {
    int e = blockIdx.x * blockDim.x + threadIdx.x;
    if (e >= E) return;
    int is64 = *flag;
    int r = eidx(ei, is64, e);
    int c = eidx(ei, is64, E + e);
    int pos = rowptr[c] + atomicAdd(&cnt[c], 1);
    srcv[pos] = r;
    nrm[pos] = dinv[r] * ew[e] * dinv[c];
}

// ---------------------------------------------------------------------------
// GEMM: C[M,128] = A[M,128] @ W[128,128]. W staged in smem (broadcast LDS128),
// A tile in smem padded to 129 to avoid bank conflicts.
#define MM_SMEM (128 * 128 * 4 + 32 * 129 * 4)
__global__ void __launch_bounds__(256) mm128_kernel(const float* __restrict__ A,
                                                    const float* __restrict__ W,
                                                    float* __restrict__ C, int M) {
    extern __shared__ float sm[];
    float* sW = sm;                  // 128*128
    float* sA = sm + 128 * 128;      // 32*129 (padded)
    int t = threadIdx.x;
    {
        float4* d = (float4*)sW;
        const float4* s = (const float4*)W;
        #pragma unroll
        for (int i = 0; i < 16; i++) d[t + i * 256] = s[t + i * 256];
    }
    int row0 = blockIdx.x * 32;
    #pragma unroll
    for (int i = 0; i < 16; i++) {
        int idx = t + i * 256;       // 0..4095
        int r = idx >> 7, c = idx & 127;
        int gr = row0 + r;
        sA[r * 129 + c] = (gr < M) ? A[gr * 128 + c] : 0.f;
    }
    __syncthreads();

    int row = t & 31, cg = t >> 5;   // 32 rows x 8 col-groups of 16
    float acc[16];
    #pragma unroll
    for (int j = 0; j < 16; j++) acc[j] = 0.f;
    const float* ap = &sA[row * 129];
    #pragma unroll 4
    for (int k = 0; k < 128; k++) {
        float a = ap[k];
        const float4* w4 = (const float4*)&sW[(k << 7) + (cg << 4)];
        float4 w0 = w4[0], w1 = w4[1], w2 = w4[2], w3 = w4[3];
        acc[0]  += a * w0.x; acc[1]  += a * w0.y; acc[2]  += a * w0.z; acc[3]  += a * w0.w;
        acc[4]  += a * w1.x; acc[5]  += a * w1.y; acc[6]  += a * w1.z; acc[7]  += a * w1.w;
        acc[8]  += a * w2.x; acc[9]  += a * w2.y; acc[10] += a * w2.z; acc[11] += a * w2.w;
        acc[12] += a * w3.x; acc[13] += a * w3.y; acc[14] += a * w3.z; acc[15] += a * w3.w;
    }
    int gr = row0 + row;
    if (gr < M) {
        float4* o = (float4*)&C[gr * 128 + (cg << 4)];
        o[0] = make_float4(acc[0],  acc[1],  acc[2],  acc[3]);
        o[1] = make_float4(acc[4],  acc[5],  acc[6],  acc[7]);
        o[2] = make_float4(acc[8],  acc[9],  acc[10], acc[11]);
        o[3] = make_float4(acc[12], acc[13], acc[14], acc[15]);
    }
}

// ---------------------------------------------------------------------------
// Gather-based SpMM, warp per destination node, fused self-loop + bias + ReLU
__global__ void __launch_bounds__(256) spmm_kernel(const float4* __restrict__ H,
                                                   const float* __restrict__ dinv,
                                                   const int* __restrict__ rowptr,
                                                   const int* __restrict__ srcv,
                                                   const float* __restrict__ nrm,
                                                   const float* __restrict__ bias,
                                                   float* __restrict__ Out, int N) {
    int gw = (blockIdx.x * blockDim.x + threadIdx.x) >> 5;
    int lane = threadIdx.x & 31;
    if (gw >= N) return;
    float di = __ldg(&dinv[gw]);
    float s = di * di;               // self-loop coefficient
    float4 h = __ldg(&H[gw * 32 + lane]);
    float4 acc;
    acc.x = s * h.x; acc.y = s * h.y; acc.z = s * h.z; acc.w = s * h.w;
    int beg = __ldg(&rowptr[gw]), end = __ldg(&rowptr[gw + 1]);
    for (int i = beg; i < end; i++) {
        int r = __ldg(&srcv[i]);
        float w = __ldg(&nrm[i]);
        float4 v = __ldg(&H[r * 32 + lane]);
        acc.x += w * v.x; acc.y += w * v.y; acc.z += w * v.z; acc.w += w * v.w;
    }
    float4 bb = __ldg(&((const float4*)bias)[lane]);
    float4 o;
    o.x = fmaxf(acc.x + bb.x, 0.f);
    o.y = fmaxf(acc.y + bb.y, 0.f);
    o.z = fmaxf(acc.z + bb.z, 0.f);
    o.w = fmaxf(acc.w + bb.w, 0.f);
    ((float4*)Out)[gw * 32 + lane] = o;
}

// ---------------------------------------------------------------------------
extern "C" void kernel_launch(void* const* d_in, const int* in_sizes, int n_in,
                              void* d_out, int out_size) {
    const float* x  = (const float*)d_in[0];
    const void*  ei = d_in[1];                 // int64 or int32 (probed on device)
    const float* ew = (const float*)d_in[2];
    const float* W1 = (const float*)d_in[3];
    const float* b1 = (const float*)d_in[4];
    const float* W2 = (const float*)d_in[5];
    const float* b2 = (const float*)d_in[6];
    float* out = (float*)d_out;

    int N = in_sizes[0] / DIM;
    int E = in_sizes[2];

    float *deg, *nrm, *H, *Z;
    int *cnt, *rowptr, *srcv, *bsum, *flag;
    cudaGetSymbolAddress((void**)&deg,    g_dinv);
    cudaGetSymbolAddress((void**)&cnt,    g_cnt);
    cudaGetSymbolAddress((void**)&rowptr, g_rowptr);
    cudaGetSymbolAddress((void**)&bsum,   g_bsum);
    cudaGetSymbolAddress((void**)&flag,   g_is64);
    cudaGetSymbolAddress((void**)&srcv,   g_src);
    cudaGetSymbolAddress((void**)&nrm,    g_nrm);
    cudaGetSymbolAddress((void**)&H,      g_H);
    cudaGetSymbolAddress((void**)&Z,      g_Z);

    int eb = (E + 255) / 256;
    int nb = (N + 255) / 256;

    probe_kernel<<<1, 32>>>((const long long*)ei, N, flag);
    zero_kernel<<<nb, 256>>>(deg, cnt, N);
    deg_hist_kernel<<<eb, 256>>>(ei, ew, flag, deg, cnt, E);
    dinv_kernel<<<nb, 256>>>(deg, N);

    int nblk = (N + 1023) / 1024;
    scan_block_kernel<<<nblk, 1024>>>(cnt, rowptr, bsum, N);
    scan_sums_kernel<<<1, 1>>>(bsum, nblk);
    add_off_kernel<<<nb, 256>>>(rowptr, bsum, cnt, N, E);

    place_kernel<<<eb, 256>>>(ei, ew, flag, deg, rowptr, cnt, srcv, nrm, E);

    cudaFuncSetAttribute(mm128_kernel,
                         cudaFuncAttributeMaxDynamicSharedMemorySize, MM_SMEM);

    int mmb = (N + 31) / 32;
    int spb = (N * 32 + 255) / 256;

    // Layer 1
    mm128_kernel<<<mmb, 256, MM_SMEM>>>(x, W1, H, N);
    spmm_kernel<<<spb, 256>>>((const float4*)H, deg, rowptr, srcv, nrm, b1, Z, N);
    // Layer 2
    mm128_kernel<<<mmb, 256, MM_SMEM>>>(Z, W2, H, N);
    spmm_kernel<<<spb, 256>>>((const float4*)H, deg, rowptr, srcv, nrm, b2, out, N);
}

// round 9
// speedup vs baseline: 1.4379x; 1.4379x over previous
#include <cuda_runtime.h>
#include <cuda_bf16.h>
#include <cstdint>

#define N_MAX 100000
#define E_MAX 1600000
#define DIM 128

// ---------------------------------------------------------------------------
// Static scratch
__device__ float g_dinv[N_MAX];
__device__ int   g_cnt[N_MAX];
__device__ int   g_rowptr[N_MAX + 1];
__device__ int   g_bsum[128];
__device__ int   g_is64;
__device__ int   g_src[E_MAX];
__device__ float g_nrm[E_MAX];
__device__ float g_H[N_MAX * DIM];
__device__ float g_Z[N_MAX * DIM];
// bf16 W^T images (hi/lo split), element (n,k) at offset n*128+k
__device__ unsigned short g_W1hi[DIM * DIM], g_W1lo[DIM * DIM];
__device__ unsigned short g_W2hi[DIM * DIM], g_W2lo[DIM * DIM];

// ---------------------------------------------------------------------------
// Edge-index dtype probe
__device__ __forceinline__ int eidx(const void* ei, int is64, int p) {
    return is64 ? (int)((const long long*)ei)[p] : ((const int*)ei)[p];
}
__global__ void probe_kernel(const long long* __restrict__ ei, int N, int* __restrict__ flag) {
    if (threadIdx.x == 0) {
        int ok = 1;
        for (int i = 0; i < 64; i++) {
            long long v = ei[i];
            if (v < 0 || v >= (long long)N) { ok = 0; break; }
        }
        *flag = ok;
    }
}

__global__ void zero_kernel(float* __restrict__ deg, int* __restrict__ cnt, int N) {
    int i = blockIdx.x * blockDim.x + threadIdx.x;
    if (i < N) { deg[i] = 0.f; cnt[i] = 0; }
}

__global__ void deg_hist_kernel(const void* __restrict__ ei, const float* __restrict__ ew,
                                const int* __restrict__ flag,
                                float* __restrict__ deg, int* __restrict__ cnt, int E) {
    int e = blockIdx.x * blockDim.x + threadIdx.x;
    if (e >= E) return;
    int is64 = *flag;
    int c = eidx(ei, is64, E + e);
    atomicAdd(&deg[c], ew[e]);
    atomicAdd(&cnt[c], 1);
}

__global__ void dinv_kernel(float* __restrict__ deg, int N) {
    int i = blockIdx.x * blockDim.x + threadIdx.x;
    if (i >= N) return;
    float d = deg[i] + 1.0f;
    deg[i] = (d > 0.f) ? rsqrtf(d) : 0.f;
}

__global__ void scan_block_kernel(const int* __restrict__ cnt, int* __restrict__ rowptr,
                                  int* __restrict__ bsum, int N) {
    __shared__ int s[1024];
    int i = blockIdx.x * 1024 + threadIdx.x;
    int v = (i < N) ? cnt[i] : 0;
    s[threadIdx.x] = v;
    __syncthreads();
    for (int off = 1; off < 1024; off <<= 1) {
        int t = (threadIdx.x >= off) ? s[threadIdx.x - off] : 0;
        __syncthreads();
        s[threadIdx.x] += t;
        __syncthreads();
    }
    if (i < N) rowptr[i] = s[threadIdx.x] - v;
    if (threadIdx.x == 1023) bsum[blockIdx.x] = s[1023];
}

__global__ void scan_sums_kernel(int* __restrict__ bsum, int nblk) {
    int run = 0;
    for (int b = 0; b < nblk; b++) { int t = bsum[b]; bsum[b] = run; run += t; }
}

__global__ void add_off_kernel(int* __restrict__ rowptr, const int* __restrict__ bsum,
                               int* __restrict__ cnt, int N, int E) {
    int i = blockIdx.x * blockDim.x + threadIdx.x;
    if (i < N) { rowptr[i] += bsum[i >> 10]; cnt[i] = 0; }
    if (i == 0) rowptr[N] = E;
}

__global__ void place_kernel(const void* __restrict__ ei, const float* __restrict__ ew,
                             const int* __restrict__ flag, const float* __restrict__ dinv,
                             const int* __restrict__ rowptr, int* __restrict__ cnt,
                             int* __restrict__ srcv, float* __restrict__ nrm, int E) {
    int e = blockIdx.x * blockDim.x + threadIdx.x;
    if (e >= E) return;
    int is64 = *flag;
    int r = eidx(ei, is64, e);
    int c = eidx(ei, is64, E + e);
    int pos = rowptr[c] + atomicAdd(&cnt[c], 1);
    srcv[pos] = r;
    nrm[pos] = dinv[r] * ew[e] * dinv[c];
}

// ---------------------------------------------------------------------------
// W prep: W^T split into bf16 hi/lo. Element (n,k) = W[k][n] at offset n*128+k.
__global__ void wprep_kernel(const float* __restrict__ W,
                             unsigned short* __restrict__ hiT,
                             unsigned short* __restrict__ loT) {
    int idx = blockIdx.x * 256 + threadIdx.x;
    if (idx >= DIM * DIM) return;
    int n = idx & 127, k = idx >> 7;
    float v = W[k * DIM + n];
    __nv_bfloat16 h = __float2bfloat16(v);
    __nv_bfloat16 l = __float2bfloat16(v - __bfloat162float(h));
    hiT[n * DIM + k] = __bfloat16_as_ushort(h);
    loT[n * DIM + k] = __bfloat16_as_ushort(l);
}

// ---------------------------------------------------------------------------
// Tensor-core GEMM via mma.sync (m16n8k16 bf16), split-bf16 3-pass.
// C[M,128] = A[M,128] @ W[128,128]; B = W^T stored [n][k].
// smem: 4 matrices of 128 rows x 136 bf16 (stride 272 B -> conflict-free frag LDS)
#define SP_U32 68                       // row stride in uint32 (136 bf16)
#define MAT_BYTES (128 * SP_U32 * 4)    // 34816
#define TC_SMEM (4 * MAT_BYTES)         // 139264

__device__ __forceinline__ void mma_bf16(float* c, uint32_t a0, uint32_t a1,
                                         uint32_t a2, uint32_t a3,
                                         uint32_t b0, uint32_t b1) {
    asm volatile(
        "mma.sync.aligned.m16n8k16.row.col.f32.bf16.bf16.f32 "
        "{%0,%1,%2,%3}, {%4,%5,%6,%7}, {%8,%9}, {%0,%1,%2,%3};"
        : "+f"(c[0]), "+f"(c[1]), "+f"(c[2]), "+f"(c[3])
        : "r"(a0), "r"(a1), "r"(a2), "r"(a3), "r"(b0), "r"(b1));
}

__global__ void __launch_bounds__(256) tcmm_kernel(const float4* __restrict__ A,
                                                   const uint32_t* __restrict__ Whi,
                                                   const uint32_t* __restrict__ Wlo,
                                                   float* __restrict__ C, int M) {
    extern __shared__ char smc[];
    uint32_t* sAh = (uint32_t*)smc;
    uint32_t* sAl = (uint32_t*)(smc + MAT_BYTES);
    uint32_t* sBh = (uint32_t*)(smc + 2 * MAT_BYTES);
    uint32_t* sBl = (uint32_t*)(smc + 3 * MAT_BYTES);
    int tid = threadIdx.x, wid = tid >> 5, lane = tid & 31;
    int row0 = blockIdx.x << 7;

    // B tiles: copy gmem bf16 images into padded rows (64 uint32 data / 68 stride)
    #pragma unroll
    for (int i = tid; i < 8192; i += 256) {
        int r = i >> 6, c = i & 63;
        sBh[r * SP_U32 + c] = Whi[i];
        sBl[r * SP_U32 + c] = Wlo[i];
    }
    // A tile: fp32 -> bf16 hi/lo split into padded rows
    #pragma unroll
    for (int i = tid; i < 4096; i += 256) {
        int row = i >> 5, c4 = i & 31;
        int gr = row0 + row;
        float4 v = make_float4(0.f, 0.f, 0.f, 0.f);
        if (gr < M) v = A[gr * 32 + c4];
        __nv_bfloat16 h0 = __float2bfloat16(v.x), h1 = __float2bfloat16(v.y);
        __nv_bfloat16 h2 = __float2bfloat16(v.z), h3 = __float2bfloat16(v.w);
        __nv_bfloat16 l0 = __float2bfloat16(v.x - __bfloat162float(h0));
        __nv_bfloat16 l1 = __float2bfloat16(v.y - __bfloat162float(h1));
        __nv_bfloat16 l2 = __float2bfloat16(v.z - __bfloat162float(h2));
        __nv_bfloat16 l3 = __float2bfloat16(v.w - __bfloat162float(h3));
        int o = row * SP_U32 + c4 * 2;
        sAh[o]     = (uint32_t)__bfloat16_as_ushort(h0) | ((uint32_t)__bfloat16_as_ushort(h1) << 16);
        sAh[o + 1] = (uint32_t)__bfloat16_as_ushort(h2) | ((uint32_t)__bfloat16_as_ushort(h3) << 16);
        sAl[o]     = (uint32_t)__bfloat16_as_ushort(l0) | ((uint32_t)__bfloat16_as_ushort(l1) << 16);
        sAl[o + 1] = (uint32_t)__bfloat16_as_ushort(l2) | ((uint32_t)__bfloat16_as_ushort(l3) << 16);
    }
    __syncthreads();

    float acc[16][4];
    #pragma unroll
    for (int t = 0; t < 16; t++) {
        acc[t][0] = 0.f; acc[t][1] = 0.f; acc[t][2] = 0.f; acc[t][3] = 0.f;
    }

    int l4 = lane >> 2, lm = lane & 3;
    int m0 = wid << 4;                       // warp's 16-row stripe

    for (int p = 0; p < 3; p++) {            // hi*hi, hi*lo(B), lo(A)*hi
        const uint32_t* Ap = (p == 2) ? sAl : sAh;
        const uint32_t* Bp = (p == 1) ? sBl : sBh;
        #pragma unroll
        for (int ks = 0; ks < 8; ks++) {
            int ku = ks * 8 + lm;            // uint32 col of this lane's k pair
            int au = (m0 + l4) * SP_U32 + ku;
            uint32_t a0 = Ap[au];
            uint32_t a1 = Ap[au + 8 * SP_U32];
            uint32_t a2 = Ap[au + 4];
            uint32_t a3 = Ap[au + 8 * SP_U32 + 4];
            #pragma unroll
            for (int nt = 0; nt < 16; nt++) {
                int bu = (nt * 8 + l4) * SP_U32 + ku;
                uint32_t b0 = Bp[bu];
                uint32_t b1 = Bp[bu + 4];
                mma_bf16(acc[nt], a0, a1, a2, a3, b0, b1);
            }
        }
    }

    // Epilogue: direct stores (float2 per reg pair)
    int r_lo = row0 + m0 + l4;
    int r_hi = r_lo + 8;
    #pragma unroll
    for (int nt = 0; nt < 16; nt++) {
        int col = nt * 8 + lm * 2;
        if (r_lo < M) {
            float2 v = make_float2(acc[nt][0], acc[nt][1]);
            *(float2*)&C[(size_t)r_lo * 128 + col] = v;
        }
        if (r_hi < M) {
            float2 v = make_float2(acc[nt][2], acc[nt][3]);
            *(float2*)&C[(size_t)r_hi * 128 + col] = v;
        }
    }
}

// ---------------------------------------------------------------------------
// Gather-based SpMM, warp per destination node, fused self-loop + bias + ReLU
__global__ void __launch_bounds__(256) spmm_kernel(const float4* __restrict__ H,
                                                   const float* __restrict__ dinv,
                                                   const int* __restrict__ rowptr,
                                                   const int* __restrict__ srcv,
                                                   const float* __restrict__ nrm,
                                                   const float* __restrict__ bias,
                                                   float* __restrict__ Out, int N) {
    int gw = (blockIdx.x * blockDim.x + threadIdx.x) >> 5;
    int lane = threadIdx.x & 31;
    if (gw >= N) return;
    float di = __ldg(&dinv[gw]);
    float s = di * di;
    float4 h = __ldg(&H[gw * 32 + lane]);
    float4 acc;
    acc.x = s * h.x; acc.y = s * h.y; acc.z = s * h.z; acc.w = s * h.w;
    int beg = __ldg(&rowptr[gw]), end = __ldg(&rowptr[gw + 1]);
    for (int i = beg; i < end; i++) {
        int r = __ldg(&srcv[i]);
        float w = __ldg(&nrm[i]);
        float4 v = __ldg(&H[r * 32 + lane]);
        acc.x += w * v.x; acc.y += w * v.y; acc.z += w * v.z; acc.w += w * v.w;
    }
    float4 bb = __ldg(&((const float4*)bias)[lane]);
    float4 o;
    o.x = fmaxf(acc.x + bb.x, 0.f);
    o.y = fmaxf(acc.y + bb.y, 0.f);
    o.z = fmaxf(acc.z + bb.z, 0.f);
    o.w = fmaxf(acc.w + bb.w, 0.f);
    ((float4*)Out)[gw * 32 + lane] = o;
}

// ---------------------------------------------------------------------------
extern "C" void kernel_launch(void* const* d_in, const int* in_sizes, int n_in,
                              void* d_out, int out_size) {
    const float* x  = (const float*)d_in[0];
    const void*  ei = d_in[1];
    const float* ew = (const float*)d_in[2];
    const float* W1 = (const float*)d_in[3];
    const float* b1 = (const float*)d_in[4];
    const float* W2 = (const float*)d_in[5];
    const float* b2 = (const float*)d_in[6];
    float* out = (float*)d_out;

    int N = in_sizes[0] / DIM;
    int E = in_sizes[2];

    float *deg, *nrm, *H, *Z;
    int *cnt, *rowptr, *srcv, *bsum, *flag;
    unsigned short *w1h, *w1l, *w2h, *w2l;
    cudaGetSymbolAddress((void**)&deg,    g_dinv);
    cudaGetSymbolAddress((void**)&cnt,    g_cnt);
    cudaGetSymbolAddress((void**)&rowptr, g_rowptr);
    cudaGetSymbolAddress((void**)&bsum,   g_bsum);
    cudaGetSymbolAddress((void**)&flag,   g_is64);
    cudaGetSymbolAddress((void**)&srcv,   g_src);
    cudaGetSymbolAddress((void**)&nrm,    g_nrm);
    cudaGetSymbolAddress((void**)&H,      g_H);
    cudaGetSymbolAddress((void**)&Z,      g_Z);
    cudaGetSymbolAddress((void**)&w1h,    g_W1hi);
    cudaGetSymbolAddress((void**)&w1l,    g_W1lo);
    cudaGetSymbolAddress((void**)&w2h,    g_W2hi);
    cudaGetSymbolAddress((void**)&w2l,    g_W2lo);

    int eb = (E + 255) / 256;
    int nb = (N + 255) / 256;

    probe_kernel<<<1, 32>>>((const long long*)ei, N, flag);
    zero_kernel<<<nb, 256>>>(deg, cnt, N);
    deg_hist_kernel<<<eb, 256>>>(ei, ew, flag, deg, cnt, E);
    dinv_kernel<<<nb, 256>>>(deg, N);

    int nblk = (N + 1023) / 1024;
    scan_block_kernel<<<nblk, 1024>>>(cnt, rowptr, bsum, N);
    scan_sums_kernel<<<1, 1>>>(bsum, nblk);
    add_off_kernel<<<nb, 256>>>(rowptr, bsum, cnt, N, E);
    place_kernel<<<eb, 256>>>(ei, ew, flag, deg, rowptr, cnt, srcv, nrm, E);

    wprep_kernel<<<64, 256>>>(W1, w1h, w1l);
    wprep_kernel<<<64, 256>>>(W2, w2h, w2l);

    cudaFuncSetAttribute(tcmm_kernel, cudaFuncAttributeMaxDynamicSharedMemorySize, TC_SMEM);

    int mmb = (N + 127) / 128;
    int spb = (N * 32 + 255) / 256;

    // Layer 1
    tcmm_kernel<<<mmb, 256, TC_SMEM>>>((const float4*)x, (const uint32_t*)w1h, (const uint32_t*)w1l, H, N);
    spmm_kernel<<<spb, 256>>>((const float4*)H, deg, rowptr, srcv, nrm, b1, Z, N);
    // Layer 2
    tcmm_kernel<<<mmb, 256, TC_SMEM>>>((const float4*)Z, (const uint32_t*)w2h, (const uint32_t*)w2l, H, N);
    spmm_kernel<<<spb, 256>>>((const float4*)H, deg, rowptr, srcv, nrm, b2, out, N);
}

// round 10
// speedup vs baseline: 1.5675x; 1.0901x over previous
#include <cuda_runtime.h>
#include <cuda_bf16.h>
#include <cuda_fp16.h>
#include <cstdint>

#define N_MAX 100000
#define E_MAX 1600000
#define DIM 128

// ---------------------------------------------------------------------------
// Static scratch
__device__ float g_dinv[N_MAX];
__device__ int   g_cnt[N_MAX];
__device__ int   g_rowptr[N_MAX + 1];
__device__ int   g_bsum[128];
__device__ int   g_is64;
__device__ int2  g_edge[E_MAX];          // packed {src, norm-as-int}
__device__ __half g_Hh[N_MAX * DIM];     // post-GEMM features (fp16)
__device__ float  g_Z[N_MAX * DIM];      // layer-1 output (fp32)
// bf16 W^T images (hi/lo split), element (n,k) at offset n*128+k
__device__ unsigned short g_W1hi[DIM * DIM], g_W1lo[DIM * DIM];
__device__ unsigned short g_W2hi[DIM * DIM], g_W2lo[DIM * DIM];

// ---------------------------------------------------------------------------
__device__ __forceinline__ int eidx(const void* ei, int is64, int p) {
    return is64 ? (int)((const long long*)ei)[p] : ((const int*)ei)[p];
}

// Zero + dtype probe fused
__global__ void zero_probe_kernel(float* __restrict__ deg, int* __restrict__ cnt,
                                  int N, const long long* __restrict__ ei,
                                  int* __restrict__ flag) {
    int i = blockIdx.x * blockDim.x + threadIdx.x;
    if (i < N) { deg[i] = 0.f; cnt[i] = 0; }
    if (blockIdx.x == 0 && threadIdx.x == 0) {
        int ok = 1;
        for (int j = 0; j < 64; j++) {
            long long v = ei[j];
            if (v < 0 || v >= (long long)N) { ok = 0; break; }
        }
        *flag = ok;
    }
}

__global__ void deg_hist_kernel(const void* __restrict__ ei, const float* __restrict__ ew,
                                const int* __restrict__ flag,
                                float* __restrict__ deg, int* __restrict__ cnt, int E) {
    int e = blockIdx.x * blockDim.x + threadIdx.x;
    if (e >= E) return;
    int is64 = *flag;
    int c = eidx(ei, is64, E + e);
    atomicAdd(&deg[c], ew[e]);
    atomicAdd(&cnt[c], 1);
}

// Block scan of cnt (exclusive) + dinv computation fused
__global__ void scan_block_kernel(const int* __restrict__ cnt, int* __restrict__ rowptr,
                                  int* __restrict__ bsum, float* __restrict__ deg, int N) {
    __shared__ int s[1024];
    int i = blockIdx.x * 1024 + threadIdx.x;
    int v = (i < N) ? cnt[i] : 0;
    s[threadIdx.x] = v;
    __syncthreads();
    for (int off = 1; off < 1024; off <<= 1) {
        int t = (threadIdx.x >= off) ? s[threadIdx.x - off] : 0;
        __syncthreads();
        s[threadIdx.x] += t;
        __syncthreads();
    }
    if (i < N) {
        rowptr[i] = s[threadIdx.x] - v;
        float d = deg[i] + 1.0f;
        deg[i] = (d > 0.f) ? rsqrtf(d) : 0.f;
    }
    if (threadIdx.x == 1023) bsum[blockIdx.x] = s[1023];
}

// Parallel scan of <=128 block sums (1 block, 128 threads)
__global__ void scan_sums_kernel(int* __restrict__ bsum, int nblk) {
    __shared__ int s[128];
    int t = threadIdx.x;
    int v = (t < nblk) ? bsum[t] : 0;
    s[t] = v;
    __syncthreads();
    for (int off = 1; off < 128; off <<= 1) {
        int u = (t >= off) ? s[t - off] : 0;
        __syncthreads();
        s[t] += u;
        __syncthreads();
    }
    if (t < nblk) bsum[t] = s[t] - v;   // exclusive
}

__global__ void add_off_kernel(int* __restrict__ rowptr, const int* __restrict__ bsum,
                               int* __restrict__ cnt, int N, int E) {
    int i = blockIdx.x * blockDim.x + threadIdx.x;
    if (i < N) { rowptr[i] += bsum[i >> 10]; cnt[i] = 0; }
    if (i == 0) rowptr[N] = E;
}

__global__ void place_kernel(const void* __restrict__ ei, const float* __restrict__ ew,
                             const int* __restrict__ flag, const float* __restrict__ dinv,
                             const int* __restrict__ rowptr, int* __restrict__ cnt,
                             int2* __restrict__ epack, int E) {
    int e = blockIdx.x * blockDim.x + threadIdx.x;
    if (e >= E) return;
    int is64 = *flag;
    int r = eidx(ei, is64, e);
    int c = eidx(ei, is64, E + e);
    int pos = rowptr[c] + atomicAdd(&cnt[c], 1);
    float nv = dinv[r] * ew[e] * dinv[c];
    epack[pos] = make_int2(r, __float_as_int(nv));
}

// ---------------------------------------------------------------------------
// W prep (both layers in one launch): W^T split into bf16 hi/lo.
__global__ void wprep_kernel(const float* __restrict__ Wa, const float* __restrict__ Wb,
                             unsigned short* __restrict__ hiA, unsigned short* __restrict__ loA,
                             unsigned short* __restrict__ hiB, unsigned short* __restrict__ loB) {
    int b = blockIdx.x;
    const float* W = (b < 64) ? Wa : Wb;
    unsigned short* hi = (b < 64) ? hiA : hiB;
    unsigned short* lo = (b < 64) ? loA : loB;
    int idx = (b & 63) * 256 + threadIdx.x;
    int n = idx & 127, k = idx >> 7;
    float v = W[k * DIM + n];
    __nv_bfloat16 h = __float2bfloat16(v);
    __nv_bfloat16 l = __float2bfloat16(v - __bfloat162float(h));
    hi[n * DIM + k] = __bfloat16_as_ushort(h);
    lo[n * DIM + k] = __bfloat16_as_ushort(l);
}

// ---------------------------------------------------------------------------
// Tensor-core GEMM via mma.sync (m16n8k16 bf16), split-bf16 3-pass.
// C_half[M,128] = A[M,128] @ W[128,128]; B = W^T stored [n][k].
#define SP_U32 68                       // row stride in uint32 (136 bf16)
#define MAT_BYTES (128 * SP_U32 * 4)    // 34816
#define TC_SMEM (4 * MAT_BYTES)         // 139264

__device__ __forceinline__ void mma_bf16(float* c, uint32_t a0, uint32_t a1,
                                         uint32_t a2, uint32_t a3,
                                         uint32_t b0, uint32_t b1) {
    asm volatile(
        "mma.sync.aligned.m16n8k16.row.col.f32.bf16.bf16.f32 "
        "{%0,%1,%2,%3}, {%4,%5,%6,%7}, {%8,%9}, {%0,%1,%2,%3};"
        : "+f"(c[0]), "+f"(c[1]), "+f"(c[2]), "+f"(c[3])
        : "r"(a0), "r"(a1), "r"(a2), "r"(a3), "r"(b0), "r"(b1));
}

__global__ void __launch_bounds__(256) tcmm_kernel(const float4* __restrict__ A,
                                                   const uint32_t* __restrict__ Whi,
                                                   const uint32_t* __restrict__ Wlo,
                                                   __half* __restrict__ C, int M) {
    extern __shared__ char smc[];
    uint32_t* sAh = (uint32_t*)smc;
    uint32_t* sAl = (uint32_t*)(smc + MAT_BYTES);
    uint32_t* sBh = (uint32_t*)(smc + 2 * MAT_BYTES);
    uint32_t* sBl = (uint32_t*)(smc + 3 * MAT_BYTES);
    int tid = threadIdx.x, wid = tid >> 5, lane = tid & 31;
    int row0 = blockIdx.x << 7;

    #pragma unroll
    for (int i = tid; i < 8192; i += 256) {
        int r = i >> 6, c = i & 63;
        sBh[r * SP_U32 + c] = Whi[i];
        sBl[r * SP_U32 + c] = Wlo[i];
    }
    #pragma unroll
    for (int i = tid; i < 4096; i += 256) {
        int row = i >> 5, c4 = i & 31;
        int gr = row0 + row;
        float4 v = make_float4(0.f, 0.f, 0.f, 0.f);
        if (gr < M) v = A[gr * 32 + c4];
        __nv_bfloat16 h0 = __float2bfloat16(v.x), h1 = __float2bfloat16(v.y);
        __nv_bfloat16 h2 = __float2bfloat16(v.z), h3 = __float2bfloat16(v.w);
        __nv_bfloat16 l0 = __float2bfloat16(v.x - __bfloat162float(h0));
        __nv_bfloat16 l1 = __float2bfloat16(v.y - __bfloat162float(h1));
        __nv_bfloat16 l2 = __float2bfloat16(v.z - __bfloat162float(h2));
        __nv_bfloat16 l3 = __float2bfloat16(v.w - __bfloat162float(h3));
        int o = row * SP_U32 + c4 * 2;
        sAh[o]     = (uint32_t)__bfloat16_as_ushort(h0) | ((uint32_t)__bfloat16_as_ushort(h1) << 16);
        sAh[o + 1] = (uint32_t)__bfloat16_as_ushort(h2) | ((uint32_t)__bfloat16_as_ushort(h3) << 16);
        sAl[o]     = (uint32_t)__bfloat16_as_ushort(l0) | ((uint32_t)__bfloat16_as_ushort(l1) << 16);
        sAl[o + 1] = (uint32_t)__bfloat16_as_ushort(l2) | ((uint32_t)__bfloat16_as_ushort(l3) << 16);
    }
    __syncthreads();

    float acc[16][4];
    #pragma unroll
    for (int t = 0; t < 16; t++) {
        acc[t][0] = 0.f; acc[t][1] = 0.f; acc[t][2] = 0.f; acc[t][3] = 0.f;
    }

    int l4 = lane >> 2, lm = lane & 3;
    int m0 = wid << 4;

    for (int p = 0; p < 3; p++) {            // hi*hi, hi*lo(B), lo(A)*hi
        const uint32_t* Ap = (p == 2) ? sAl : sAh;
        const uint32_t* Bp = (p == 1) ? sBl : sBh;
        #pragma unroll
        for (int ks = 0; ks < 8; ks++) {
            int ku = ks * 8 + lm;
            int au = (m0 + l4) * SP_U32 + ku;
            uint32_t a0 = Ap[au];
            uint32_t a1 = Ap[au + 8 * SP_U32];
            uint32_t a2 = Ap[au + 4];
            uint32_t a3 = Ap[au + 8 * SP_U32 + 4];
            #pragma unroll
            for (int nt = 0; nt < 16; nt++) {
                int bu = (nt * 8 + l4) * SP_U32 + ku;
                mma_bf16(acc[nt], a0, a1, a2, a3, Bp[bu], Bp[bu + 4]);
            }
        }
    }

    // Epilogue: fp16 stores
    int r_lo = row0 + m0 + l4;
    int r_hi = r_lo + 8;
    #pragma unroll
    for (int nt = 0; nt < 16; nt++) {
        int col = nt * 8 + lm * 2;
        if (r_lo < M)
            *(__half2*)&C[(size_t)r_lo * 128 + col] =
                __float22half2_rn(make_float2(acc[nt][0], acc[nt][1]));
        if (r_hi < M)
            *(__half2*)&C[(size_t)r_hi * 128 + col] =
                __float22half2_rn(make_float2(acc[nt][2], acc[nt][3]));
    }
}

// ---------------------------------------------------------------------------
// Gather-based SpMM on fp16 features, fp32 accumulation.
// Warp per destination node; fused self-loop + bias + ReLU; fp32 output.
__global__ void __launch_bounds__(256) spmm_kernel(const uint2* __restrict__ Hh,
                                                   const float* __restrict__ dinv,
                                                   const int* __restrict__ rowptr,
                                                   const int2* __restrict__ epack,
                                                   const float* __restrict__ bias,
                                                   float* __restrict__ Out, int N) {
    int gw = (blockIdx.x * blockDim.x + threadIdx.x) >> 5;
    int lane = threadIdx.x & 31;
    if (gw >= N) return;
    float di = __ldg(&dinv[gw]);
    float s = di * di;
    uint2 hv = __ldg(&Hh[(size_t)gw * 32 + lane]);
    float2 h0 = __half22float2(*(__half2*)&hv.x);
    float2 h1 = __half22float2(*(__half2*)&hv.y);
    float4 acc = make_float4(s * h0.x, s * h0.y, s * h1.x, s * h1.y);
    int beg = __ldg(&rowptr[gw]), end = __ldg(&rowptr[gw + 1]);
    #pragma unroll 4
    for (int i = beg; i < end; i++) {
        int2 e = __ldg(&epack[i]);
        float w = __int_as_float(e.y);
        uint2 v = __ldg(&Hh[(size_t)e.x * 32 + lane]);
        float2 f0 = __half22float2(*(__half2*)&v.x);
        float2 f1 = __half22float2(*(__half2*)&v.y);
        acc.x += w * f0.x; acc.y += w * f0.y;
        acc.z += w * f1.x; acc.w += w * f1.y;
    }
    float4 bb = __ldg(&((const float4*)bias)[lane]);
    float4 o;
    o.x = fmaxf(acc.x + bb.x, 0.f);
    o.y = fmaxf(acc.y + bb.y, 0.f);
    o.z = fmaxf(acc.z + bb.z, 0.f);
    o.w = fmaxf(acc.w + bb.w, 0.f);
    ((float4*)Out)[(size_t)gw * 32 + lane] = o;
}

// ---------------------------------------------------------------------------
extern "C" void kernel_launch(void* const* d_in, const int* in_sizes, int n_in,
                              void* d_out, int out_size) {
    const float* x  = (const float*)d_in[0];
    const void*  ei = d_in[1];
    const float* ew = (const float*)d_in[2];
    const float* W1 = (const float*)d_in[3];
    const float* b1 = (const float*)d_in[4];
    const float* W2 = (const float*)d_in[5];
    const float* b2 = (const float*)d_in[6];
    float* out = (float*)d_out;

    int N = in_sizes[0] / DIM;
    int E = in_sizes[2];

    float *deg, *Z;
    __half* Hh;
    int *cnt, *rowptr, *bsum, *flag;
    int2* epack;
    unsigned short *w1h, *w1l, *w2h, *w2l;
    cudaGetSymbolAddress((void**)&deg,    g_dinv);
    cudaGetSymbolAddress((void**)&cnt,    g_cnt);
    cudaGetSymbolAddress((void**)&rowptr, g_rowptr);
    cudaGetSymbolAddress((void**)&bsum,   g_bsum);
    cudaGetSymbolAddress((void**)&flag,   g_is64);
    cudaGetSymbolAddress((void**)&epack,  g_edge);
    cudaGetSymbolAddress((void**)&Hh,     g_Hh);
    cudaGetSymbolAddress((void**)&Z,      g_Z);
    cudaGetSymbolAddress((void**)&w1h,    g_W1hi);
    cudaGetSymbolAddress((void**)&w1l,    g_W1lo);
    cudaGetSymbolAddress((void**)&w2h,    g_W2hi);
    cudaGetSymbolAddress((void**)&w2l,    g_W2lo);

    int eb = (E + 255) / 256;
    int nb = (N + 255) / 256;

    zero_probe_kernel<<<nb, 256>>>(deg, cnt, N, (const long long*)ei, flag);
    deg_hist_kernel<<<eb, 256>>>(ei, ew, flag, deg, cnt, E);

    int nblk = (N + 1023) / 1024;
    scan_block_kernel<<<nblk, 1024>>>(cnt, rowptr, bsum, deg, N);
    scan_sums_kernel<<<1, 128>>>(bsum, nblk);
    add_off_kernel<<<nb, 256>>>(rowptr, bsum, cnt, N, E);
    place_kernel<<<eb, 256>>>(ei, ew, flag, deg, rowptr, cnt, epack, E);

    wprep_kernel<<<128, 256>>>(W1, W2, w1h, w1l, w2h, w2l);

    cudaFuncSetAttribute(tcmm_kernel, cudaFuncAttributeMaxDynamicSharedMemorySize, TC_SMEM);

    int mmb = (N + 127) / 128;
    int spb = (N * 32 + 255) / 256;

    // Layer 1
    tcmm_kernel<<<mmb, 256, TC_SMEM>>>((const float4*)x, (const uint32_t*)w1h, (const uint32_t*)w1l, Hh, N);
    spmm_kernel<<<spb, 256>>>((const uint2*)Hh, deg, rowptr, epack, b1, Z, N);
    // Layer 2
    tcmm_kernel<<<mmb, 256, TC_SMEM>>>((const float4*)Z, (const uint32_t*)w2h, (const uint32_t*)w2l, Hh, N);
    spmm_kernel<<<spb, 256>>>((const uint2*)Hh, deg, rowptr, epack, b2, out, N);
}